// round 11
// baseline (speedup 1.0000x reference)
#include <cuda_runtime.h>
#include <math.h>

#define BATCH 2
#define NP    4096
#define HH    128
#define WW    128
#define KK    8
#define RAD   0.05f
#define RAD2  (RAD * RAD)
#define NPIXT (BATCH * HH * WW)   // 32768 pixels total
#define CAP   96                  // per-pixel list capacity (λ≈20 → huge margin)
#define THREADS 128
#define NCTA  (NPIXT / THREADS)   // 256

#define ZINF 3.0e38f

// Global scratch (no cudaMalloc allowed). Slot-major for coalesced raster reads.
__device__ int      g_cnt[NPIXT];             // zero-init; reset in-kernel
__device__ float    g_z[CAP * NPIXT];         // 12.6 MB
__device__ float2   g_pay[CAP * NPIXT];       // 25 MB  (d2, idx)
__device__ unsigned g_arrive = 0;
__device__ unsigned g_epoch  = 0;             // monotonic across replays

__global__ void __launch_bounds__(THREADS, 4) raster_fused(
        const float* __restrict__ pts,
        const float* __restrict__ Rm,
        const float* __restrict__ Tv,
        const float* __restrict__ Fc,
        float* __restrict__ out) {
    const int tid  = threadIdx.x;
    const int gtid = blockIdx.x * THREADS + tid;

    // ====== Phase 1: transform + per-pixel exact-test binning ================
    // Every 4th thread handles one point -> work spread over ALL CTAs/SMs.
    if ((gtid & 3) == 0) {
        int t = gtid >> 2;                    // 0..8191
        int pb = t / NP;
        int p  = t - pb * NP;
        float p0 = pts[t * 3 + 0];
        float p1 = pts[t * 3 + 1];
        float p2 = pts[t * 3 + 2];
        const float* Rb = Rm + pb * 9;
        const float* Tb = Tv + pb * 3;

        // row-vector: v[j] = sum_i p[i]*R[i][j] + T[j]
        float xv = p0 * Rb[0] + p1 * Rb[3] + p2 * Rb[6] + Tb[0];
        float yv = p0 * Rb[1] + p1 * Rb[4] + p2 * Rb[7] + Tb[1];
        float zv = p0 * Rb[2] + p1 * Rb[5] + p2 * Rb[8] + Tb[2];

        float f = Fc[pb];
        float x = f * xv / zv;                // IEEE div, matches reference
        float y = f * yv / zv;

        if (zv > 0.0f) {
            // conservative pixel bbox: |gx(ix) - x| < r, gx(ix) = 1-(ix+0.5)/64
            float lox = 64.0f * (1.0f - x - RAD) - 0.5f;
            float hix = 64.0f * (1.0f - x + RAD) - 0.5f;
            float loy = 64.0f * (1.0f - y - RAD) - 0.5f;
            float hiy = 64.0f * (1.0f - y + RAD) - 0.5f;
            if (hix >= 0.0f && lox <= (float)(WW - 1) &&
                hiy >= 0.0f && loy <= (float)(HH - 1)) {
                int ix0 = max(0, (int)floorf(fmaxf(lox, 0.0f)));
                int ix1 = min(WW - 1, (int)ceilf(fminf(hix, (float)(WW - 1))));
                int iy0 = max(0, (int)floorf(fmaxf(loy, 0.0f)));
                int iy1 = min(HH - 1, (int)ceilf(fminf(hiy, (float)(HH - 1))));
                float idxf = (float)p;
                for (int iy = iy0; iy <= iy1; iy++) {
                    float gyp = 1.0f - (iy + 0.5f) * (1.0f / 64.0f);
                    float dy  = gyp - y;
                    float dy2 = dy * dy;
                    for (int ix = ix0; ix <= ix1; ix++) {
                        float gxp = 1.0f - (ix + 0.5f) * (1.0f / 64.0f);
                        float dx  = gxp - x;
                        float d2  = fmaf(dx, dx, dy2);
                        if (d2 < RAD2) {                 // exact circle test HERE
                            int pix = pb * (HH * WW) + iy * WW + ix;
                            int slot = atomicAdd(&g_cnt[pix], 1);
                            if (slot < CAP) {
                                g_z[slot * NPIXT + pix]   = zv;
                                g_pay[slot * NPIXT + pix] = make_float2(d2, idxf);
                            }
                        }
                    }
                }
            }
        }
    }

    // ====== Grid-wide barrier (256 CTAs, co-resident single wave) ============
    __threadfence();
    __syncthreads();
    if (tid == 0) {
        unsigned e = *(volatile unsigned*)&g_epoch;
        __threadfence();
        unsigned a = atomicAdd(&g_arrive, 1u);
        if (a == NCTA - 1) {
            g_arrive = 0;
            __threadfence();
            atomicAdd(&g_epoch, 1u);
        } else {
            while (*(volatile unsigned*)&g_epoch == e) __nanosleep(64);
        }
        __threadfence();
    }
    __syncthreads();

    // ====== Phase 2: per-pixel top-8 over TRUE HITS only =====================
    const int pix = gtid;                     // 1 thread per pixel
    int n = g_cnt[pix];
    g_cnt[pix] = 0;                           // reset for next graph replay
    n = min(n, CAP);

    float zb[KK];
#pragma unroll
    for (int k = 0; k < KK; k++) zb[k] = ZINF;

    // Pass 1: branch-free FMNMX ladder over z (all records are hits)
    for (int j = 0; j < n; j++) {
        float key = g_z[j * NPIXT + pix];     // coalesced across warp
#pragma unroll
        for (int k = 0; k < KK; k++) {
            float lo = fminf(zb[k], key);
            key = fmaxf(zb[k], key);
            zb[k] = lo;
        }
    }
    const float z7 = zb[KK - 1];

    float db[KK], ib[KK];
#pragma unroll
    for (int k = 0; k < KK; k++) { db[k] = -1.0f; ib[k] = -1.0f; }

    // Pass 2: sparse equality fill of d2/idx (z values distinct)
    for (int j = 0; j < n; j++) {
        float zj = g_z[j * NPIXT + pix];
        if (zj <= z7) {
            float2 pay = g_pay[j * NPIXT + pix];
#pragma unroll
            for (int k = 0; k < KK; k++) {
                if (zj == zb[k]) { db[k] = pay.x; ib[k] = pay.y; }
            }
        }
    }

    // ---- Output: [idx | zbuf | dists], each [B,H,W,K] ----
    const int N = NPIXT * KK;
    const int obase = pix * KK;
#pragma unroll
    for (int k = 0; k < KK; k++) {
        bool v = zb[k] < ZINF;
        out[obase + k]         = v ? ib[k] : -1.0f;
        out[N + obase + k]     = v ? zb[k] : -1.0f;
        out[2 * N + obase + k] = v ? db[k] : -1.0f;
    }
}

// ---------------------------------------------------------------------------
extern "C" void kernel_launch(void* const* d_in, const int* in_sizes, int n_in,
                              void* d_out, int out_size) {
    const float* pts = (const float*)d_in[0];
    const float* Rm  = (const float*)d_in[1];
    const float* Tv  = (const float*)d_in[2];
    const float* Fc  = (const float*)d_in[3];
    float* out = (float*)d_out;

    raster_fused<<<NCTA, THREADS>>>(pts, Rm, Tv, Fc, out);
}

// round 12
// speedup vs baseline: 2.0097x; 2.0097x over previous
#include <cuda_runtime.h>
#include <math.h>

#define BATCH 2
#define NP    4096
#define HH    128
#define WW    128
#define KK    8
#define RAD   0.05f
#define RAD2  (RAD * RAD)
#define TILE  8
#define TX    (WW / TILE)    // 16
#define TYN   (HH / TILE)    // 16
#define NTILES (TX * TYN)    // 256
#define NCTA  (TX * TYN * BATCH)  // 512
#define THREADS 128          // 4 warps: 2 pixel-blocks x 2 stride-warps
#define PTS_PER_CTA ((BATCH * NP) / NCTA)  // 16
#define CHUNK 512

#define ZINF 3.0e38f

// Global scratch (no cudaMalloc allowed)
__device__ int      g_cnt[BATCH * NTILES];       // zero-init; reset in-kernel
__device__ float4   g_list[BATCH * NTILES * NP]; // per-tile capacity NP: un-overflowable
__device__ unsigned g_arrive = 0;
__device__ unsigned g_epoch  = 0;                // monotonic across replays

__global__ void __launch_bounds__(THREADS, 4) raster_fused(
        const float* __restrict__ pts,
        const float* __restrict__ Rm,
        const float* __restrict__ Tv,
        const float* __restrict__ Fc,
        float* __restrict__ out) {
    __shared__ float4 sc[CHUNK];            // 8 KB candidate staging
    __shared__ float  s_m[2][4][32][KK];    // 8 KB merge area (z, then db/ib)
    __shared__ int s_n;

    const int bx = blockIdx.x, by = blockIdx.y, b = blockIdx.z;
    const int cta = bx + TX * (by + TYN * b);
    const int tid = threadIdx.x;
    const int w    = tid >> 5;              // warp 0..3
    const int lane = tid & 31;
    const int blockrow = w >> 1;            // pixel-block: rows [4*blockrow, 4*blockrow+4)
    const int sub = w & 1;                  // candidate stride within block

    // ====== Phase 1: transform + bin (16 pts per CTA, threads 0..15) =========
    if (tid < PTS_PER_CTA) {
        int t = cta * PTS_PER_CTA + tid;
        int pb = t / NP;
        int p  = t - pb * NP;
        float p0 = pts[t * 3 + 0];
        float p1 = pts[t * 3 + 1];
        float p2 = pts[t * 3 + 2];
        const float* Rb = Rm + pb * 9;
        const float* Tb = Tv + pb * 3;

        // row-vector: v[j] = sum_i p[i]*R[i][j] + T[j]
        float xv = p0 * Rb[0] + p1 * Rb[3] + p2 * Rb[6] + Tb[0];
        float yv = p0 * Rb[1] + p1 * Rb[4] + p2 * Rb[7] + Tb[1];
        float zv = p0 * Rb[2] + p1 * Rb[5] + p2 * Rb[8] + Tb[2];

        float f = Fc[pb];
        float x = f * xv / zv;   // IEEE div, matches reference
        float y = f * yv / zv;

        if (zv > 0.0f) {
            float lox = 64.0f * (1.0f - x - RAD) - 0.5f;
            float hix = 64.0f * (1.0f - x + RAD) - 0.5f;
            float loy = 64.0f * (1.0f - y - RAD) - 0.5f;
            float hiy = 64.0f * (1.0f - y + RAD) - 0.5f;
            if (hix >= 0.0f && lox <= (float)(WW - 1) &&
                hiy >= 0.0f && loy <= (float)(HH - 1)) {
                int ix0 = max(0, (int)floorf(fmaxf(lox, 0.0f)));
                int ix1 = min(WW - 1, (int)ceilf(fminf(hix, (float)(WW - 1))));
                int iy0 = max(0, (int)floorf(fmaxf(loy, 0.0f)));
                int iy1 = min(HH - 1, (int)ceilf(fminf(hiy, (float)(HH - 1))));
                if (ix0 <= ix1 && iy0 <= iy1) {
                    int tx0 = ix0 / TILE, tx1 = ix1 / TILE;
                    int ty0 = iy0 / TILE, ty1 = iy1 / TILE;
                    float4 rec = make_float4(x, y, zv, (float)p);
                    for (int ty = ty0; ty <= ty1; ty++)
                        for (int tx = tx0; tx <= tx1; tx++) {
                            int tile = pb * NTILES + ty * TX + tx;
                            int pos = atomicAdd(&g_cnt[tile], 1);
                            g_list[tile * NP + pos] = rec;
                        }
                }
            }
        }
    }

    // ====== Grid-wide barrier (512 CTAs, single co-resident wave) ============
    __threadfence();
    __syncthreads();
    if (tid == 0) {
        unsigned e = *(volatile unsigned*)&g_epoch;
        __threadfence();
        unsigned a = atomicAdd(&g_arrive, 1u);
        if (a == NCTA - 1) {
            g_arrive = 0;
            __threadfence();
            atomicAdd(&g_epoch, 1u);
        } else {
            while (*(volatile unsigned*)&g_epoch == e) __nanosleep(64);
        }
        __threadfence();
    }
    __syncthreads();

    // ====== Phase 2: raster — lane = pixel, warp-vote ladder skip ============
    const int tile = b * NTILES + by * TX + bx;
    if (tid == 0) {
        s_n = g_cnt[tile];
        g_cnt[tile] = 0;          // reset for next graph replay (own counter)
    }
    __syncthreads();
    const int n = s_n;
    const float4* __restrict__ list = g_list + tile * NP;

    const int lx = lane & 7;                 // pixel within 8x4 block
    const int lyb = lane >> 3;
    const int px = bx * TILE + lx;
    const int py = by * TILE + blockrow * 4 + lyb;
    const float gx = 1.0f - (px + 0.5f) * (1.0f / 64.0f);
    const float gy = 1.0f - (py + 0.5f) * (1.0f / 64.0f);

    float zb[KK];
#pragma unroll
    for (int k = 0; k < KK; k++) zb[k] = ZINF;

    // ---- Pass 1 (chunked): broadcast candidate, vote-guarded FMNMX ladder ---
    for (int base = 0; base < n; base += CHUNK) {
        int m = min(CHUNK, n - base);
        __syncthreads();
        for (int i = tid; i < m; i += THREADS) sc[i] = list[base + i];
        __syncthreads();
        for (int j = sub; j < m; j += 2) {
            float4 c = sc[j];                // same addr for all lanes: broadcast
            float dx = gx - c.x;
            float dy = gy - c.y;
            float d2 = fmaf(dx, dx, dy * dy);
            bool hit = d2 < RAD2;
            if (__any_sync(0xffffffffu, hit)) {   // warp-uniform skip (~70% miss)
                float key = hit ? c.z : ZINF;
#pragma unroll
                for (int k = 0; k < KK; k++) {
                    float lo = fminf(zb[k], key);
                    key = fmaxf(zb[k], key);
                    zb[k] = lo;
                }
            }
        }
    }

    // ---- merge the two stride-warps' sorted lists (smem + bitonic) ----------
    {
#pragma unroll
        for (int k = 0; k < KK; k++) s_m[0][w][lane][k] = zb[k];
        __syncthreads();
        float L[KK];
#pragma unroll
        for (int k = 0; k < KK; k++) {
            float bk = s_m[0][w ^ 1][lane][KK - 1 - k];
            L[k] = fminf(zb[k], bk);         // lower half of bitonic merge
        }
#define CE(a, b2) { float lo = fminf(L[a], L[b2]); float hi = fmaxf(L[a], L[b2]); L[a] = lo; L[b2] = hi; }
        CE(0, 4) CE(1, 5) CE(2, 6) CE(3, 7)
        CE(0, 2) CE(1, 3) CE(4, 6) CE(5, 7)
        CE(0, 1) CE(2, 3) CE(4, 5) CE(6, 7)
#undef CE
#pragma unroll
        for (int k = 0; k < KK; k++) zb[k] = L[k];
    }
    const float z7 = zb[KK - 1];

    float db[KK], ib[KK];
#pragma unroll
    for (int k = 0; k < KK; k++) { db[k] = -1.0f; ib[k] = -1.0f; }

    // ---- Pass 2 (chunked): sparse equality fill (z distinct), vote-guarded --
    for (int base = 0; base < n; base += CHUNK) {
        int m = min(CHUNK, n - base);
        if (n > CHUNK) {                     // restage only if list didn't fit
            __syncthreads();
            for (int i = tid; i < m; i += THREADS) sc[i] = list[base + i];
            __syncthreads();
        }
        for (int j = sub; j < m; j += 2) {
            float4 c = sc[j];
            float dx = gx - c.x;
            float dy = gy - c.y;
            float d2 = fmaf(dx, dx, dy * dy);
            bool sel = (d2 < RAD2) && (c.z <= z7);
            if (__any_sync(0xffffffffu, sel)) {
                if (sel) {
#pragma unroll
                    for (int k = 0; k < KK; k++) {
                        if (c.z == zb[k]) { db[k] = d2; ib[k] = c.w; }
                    }
                }
            }
        }
    }

    // ---- combine fills across the two stride-warps (max; unfilled = -1) -----
    __syncthreads();
#pragma unroll
    for (int k = 0; k < KK; k++) {
        s_m[0][w][lane][k] = db[k];
        s_m[1][w][lane][k] = ib[k];
    }
    __syncthreads();
    if (sub == 0) {
#pragma unroll
        for (int k = 0; k < KK; k++) {
            db[k] = fmaxf(db[k], s_m[0][w ^ 1][lane][k]);
            ib[k] = fmaxf(ib[k], s_m[1][w ^ 1][lane][k]);
        }

        // ---- Output: [idx | zbuf | dists], each [B,H,W,K] ----
        const int N = BATCH * HH * WW * KK;
        const int obase = ((b * HH + py) * WW + px) * KK;
#pragma unroll
        for (int k = 0; k < KK; k++) {
            bool v = zb[k] < ZINF;
            out[obase + k]         = v ? ib[k] : -1.0f;
            out[N + obase + k]     = v ? zb[k] : -1.0f;
            out[2 * N + obase + k] = v ? db[k] : -1.0f;
        }
    }
}

// ---------------------------------------------------------------------------
extern "C" void kernel_launch(void* const* d_in, const int* in_sizes, int n_in,
                              void* d_out, int out_size) {
    const float* pts = (const float*)d_in[0];
    const float* Rm  = (const float*)d_in[1];
    const float* Tv  = (const float*)d_in[2];
    const float* Fc  = (const float*)d_in[3];
    float* out = (float*)d_out;

    raster_fused<<<dim3(TX, TYN, BATCH), THREADS>>>(pts, Rm, Tv, Fc, out);
}

// round 13
// speedup vs baseline: 2.2122x; 1.1008x over previous
#include <cuda_runtime.h>
#include <math.h>

#define BATCH 2
#define NP    4096
#define HH    128
#define WW    128
#define KK    8
#define RAD   0.05f
#define RAD2  (RAD * RAD)
#define QT    4              // bin tile size (4x4 px)
#define QTX   (WW / QT)      // 32
#define QTYN  (HH / QT)      // 32
#define NQT   (QTX * QTYN)   // 1024 bins per batch
#define CTILE 8              // CTA covers 8x8 px = 4 quadrant bins
#define TX    (WW / CTILE)   // 16
#define TYN   (HH / CTILE)   // 16
#define NCTA  (TX * TYN * BATCH)  // 512
#define LPP   4
#define THREADS 256          // 4 quadrants x 16 px x 4 lanes
#define PTS_PER_CTA ((BATCH * NP) / NCTA)  // 16
#define CAP   1024           // per-bin capacity (proven in R10)
#define CHUNK 512

#define ZINF 3.0e38f

// Global scratch (no cudaMalloc allowed)
__device__ int      g_cnt[BATCH * NQT];          // zero-init; reset in-kernel
__device__ float4   g_list[BATCH * NQT * CAP];   // 32 MB
__device__ unsigned g_arrive = 0;
__device__ unsigned g_epoch  = 0;                // monotonic across replays

__global__ void __launch_bounds__(THREADS, 4) raster_fused(
        const float* __restrict__ pts,
        const float* __restrict__ Rm,
        const float* __restrict__ Tv,
        const float* __restrict__ Fc,
        float* __restrict__ out) {
    __shared__ float4 sc[4][CHUNK];   // 32 KB: per-quadrant staging
    __shared__ int s_nq[4];

    const int bx = blockIdx.x, by = blockIdx.y, b = blockIdx.z;
    const int cta = bx + TX * (by + TYN * b);
    const int tid = threadIdx.x;

    // ====== Phase 1: transform + bin to 4x4 tiles (16 pts per CTA) ==========
    if (tid < PTS_PER_CTA) {
        int t = cta * PTS_PER_CTA + tid;
        int pb = t / NP;
        int p  = t - pb * NP;
        float p0 = pts[t * 3 + 0];
        float p1 = pts[t * 3 + 1];
        float p2 = pts[t * 3 + 2];
        const float* Rb = Rm + pb * 9;
        const float* Tb = Tv + pb * 3;

        // row-vector: v[j] = sum_i p[i]*R[i][j] + T[j]
        float xv = p0 * Rb[0] + p1 * Rb[3] + p2 * Rb[6] + Tb[0];
        float yv = p0 * Rb[1] + p1 * Rb[4] + p2 * Rb[7] + Tb[1];
        float zv = p0 * Rb[2] + p1 * Rb[5] + p2 * Rb[8] + Tb[2];

        float f = Fc[pb];
        float x = f * xv / zv;   // IEEE div, matches reference
        float y = f * yv / zv;

        if (zv > 0.0f) {
            float lox = 64.0f * (1.0f - x - RAD) - 0.5f;
            float hix = 64.0f * (1.0f - x + RAD) - 0.5f;
            float loy = 64.0f * (1.0f - y - RAD) - 0.5f;
            float hiy = 64.0f * (1.0f - y + RAD) - 0.5f;
            if (hix >= 0.0f && lox <= (float)(WW - 1) &&
                hiy >= 0.0f && loy <= (float)(HH - 1)) {
                int ix0 = max(0, (int)floorf(fmaxf(lox, 0.0f)));
                int ix1 = min(WW - 1, (int)ceilf(fminf(hix, (float)(WW - 1))));
                int iy0 = max(0, (int)floorf(fmaxf(loy, 0.0f)));
                int iy1 = min(HH - 1, (int)ceilf(fminf(hiy, (float)(HH - 1))));
                if (ix0 <= ix1 && iy0 <= iy1) {
                    int tx0 = ix0 / QT, tx1 = ix1 / QT;
                    int ty0 = iy0 / QT, ty1 = iy1 / QT;
                    float4 rec = make_float4(x, y, zv, (float)p);
                    for (int ty = ty0; ty <= ty1; ty++)
                        for (int tx = tx0; tx <= tx1; tx++) {
                            int bin = pb * NQT + ty * QTX + tx;
                            int pos = atomicAdd(&g_cnt[bin], 1);
                            if (pos < CAP) g_list[bin * CAP + pos] = rec;
                        }
                }
            }
        }
    }

    // ====== Grid-wide barrier (512 CTAs, single co-resident wave) ============
    __threadfence();
    __syncthreads();
    if (tid == 0) {
        unsigned e = *(volatile unsigned*)&g_epoch;
        __threadfence();
        unsigned a = atomicAdd(&g_arrive, 1u);
        if (a == NCTA - 1) {
            g_arrive = 0;
            __threadfence();
            atomicAdd(&g_epoch, 1u);
        } else {
            while (*(volatile unsigned*)&g_epoch == e) __nanosleep(64);
        }
        __threadfence();
    }
    __syncthreads();

    // ====== Phase 2: raster — 4 quadrants, 16 px x 4 lanes each ==============
    const int q    = tid >> 6;       // quadrant 0..3
    const int t64  = tid & 63;
    const int pix  = t64 >> 2;       // pixel within 4x4 quadrant
    const int sub  = t64 & 3;        // lane within pixel
    const int qx = q & 1, qy = q >> 1;
    const int qtx = bx * 2 + qx, qty = by * 2 + qy;
    const int bin = b * NQT + qty * QTX + qtx;

    if (t64 == 0) {
        int c = g_cnt[bin];
        s_nq[q] = min(c, CAP);
        g_cnt[bin] = 0;              // reset for next graph replay (own bin)
    }
    __syncthreads();
    const int n = s_nq[q];
    const int n_max = max(max(s_nq[0], s_nq[1]), max(s_nq[2], s_nq[3]));
    const float4* __restrict__ list = g_list + bin * CAP;

    const int px = bx * CTILE + qx * QT + (pix & 3);
    const int py = by * CTILE + qy * QT + (pix >> 2);
    const float gx = 1.0f - (px + 0.5f) * (1.0f / 64.0f);
    const float gy = 1.0f - (py + 0.5f) * (1.0f / 64.0f);

    float zb[KK];
#pragma unroll
    for (int k = 0; k < KK; k++) zb[k] = ZINF;

    // ---- Pass 1 (chunked): branch-free FMNMX ladder, lane scans j%4==sub ----
    for (int base = 0; base < n_max; base += CHUNK) {
        int m = min(CHUNK, max(0, n - base));
        __syncthreads();
        for (int i = t64; i < m; i += 64) sc[q][i] = list[base + i];
        __syncthreads();
        for (int j = sub; j < m; j += LPP) {
            float4 c = sc[q][j];
            float dx = gx - c.x;
            float dy = gy - c.y;
            float d2 = fmaf(dx, dx, dy * dy);
            float key = (d2 < RAD2) ? c.z : ZINF;
#pragma unroll
            for (int k = 0; k < KK; k++) {
                float lo = fminf(zb[k], key);
                key = fmaxf(zb[k], key);
                zb[k] = lo;
            }
        }
    }

    // ---- merge 4 sorted lists: two bitonic-merge rounds (xor 1, xor 2) ------
#pragma unroll
    for (int d = 1; d <= 2; d <<= 1) {
        float L[KK];
#pragma unroll
        for (int k = 0; k < KK; k++) {
            float bk = __shfl_xor_sync(0xffffffffu, zb[KK - 1 - k], d);
            L[k] = fminf(zb[k], bk);          // lower half of bitonic merge
        }
#define CE(a, b2) { float lo = fminf(L[a], L[b2]); float hi = fmaxf(L[a], L[b2]); L[a] = lo; L[b2] = hi; }
        CE(0, 4) CE(1, 5) CE(2, 6) CE(3, 7)
        CE(0, 2) CE(1, 3) CE(4, 6) CE(5, 7)
        CE(0, 1) CE(2, 3) CE(4, 5) CE(6, 7)
#undef CE
#pragma unroll
        for (int k = 0; k < KK; k++) zb[k] = L[k];
    }
    const float z7 = zb[KK - 1];

    float db[KK], ib[KK];
#pragma unroll
    for (int k = 0; k < KK; k++) { db[k] = -1.0f; ib[k] = -1.0f; }

    // ---- Pass 2 (chunked): sparse equality fill of d2/idx (z distinct) ------
    for (int base = 0; base < n_max; base += CHUNK) {
        int m = min(CHUNK, max(0, n - base));
        if (n_max > CHUNK) {                  // restage only if lists didn't fit
            __syncthreads();
            for (int i = t64; i < m; i += 64) sc[q][i] = list[base + i];
            __syncthreads();
        }
        for (int j = sub; j < m; j += LPP) {
            float4 c = sc[q][j];
            float dx = gx - c.x;
            float dy = gy - c.y;
            float d2 = fmaf(dx, dx, dy * dy);
            if (d2 < RAD2 && c.z <= z7) {
#pragma unroll
                for (int k = 0; k < KK; k++) {
                    if (c.z == zb[k]) { db[k] = d2; ib[k] = c.w; }
                }
            }
        }
    }

    // ---- combine lane fills (unfilled = -1, filled >= 0 => max) -------------
#pragma unroll
    for (int d = 1; d <= 2; d <<= 1) {
#pragma unroll
        for (int k = 0; k < KK; k++) {
            db[k] = fmaxf(db[k], __shfl_xor_sync(0xffffffffu, db[k], d));
            ib[k] = fmaxf(ib[k], __shfl_xor_sync(0xffffffffu, ib[k], d));
        }
    }

    // ---- Output: [idx | zbuf | dists], each [B,H,W,K]; lanes split k --------
    const int N = BATCH * HH * WW * KK;
    const int obase = ((b * HH + py) * WW + px) * KK;
#pragma unroll
    for (int k2 = 0; k2 < KK / LPP; k2++) {
        int k = sub * (KK / LPP) + k2;
        bool v = zb[k] < ZINF;
        out[obase + k]         = v ? ib[k] : -1.0f;
        out[N + obase + k]     = v ? zb[k] : -1.0f;
        out[2 * N + obase + k] = v ? db[k] : -1.0f;
    }
}

// ---------------------------------------------------------------------------
extern "C" void kernel_launch(void* const* d_in, const int* in_sizes, int n_in,
                              void* d_out, int out_size) {
    const float* pts = (const float*)d_in[0];
    const float* Rm  = (const float*)d_in[1];
    const float* Tv  = (const float*)d_in[2];
    const float* Fc  = (const float*)d_in[3];
    float* out = (float*)d_out;

    raster_fused<<<dim3(TX, TYN, BATCH), THREADS>>>(pts, Rm, Tv, Fc, out);
}

// round 14
// speedup vs baseline: 3.4924x; 1.5787x over previous
#include <cuda_runtime.h>
#include <math.h>

#define BATCH 2
#define NP    4096
#define HH    128
#define WW    128
#define KK    8
#define RAD   0.05f
#define RAD2  (RAD * RAD)
#define TILE  8
#define TX    (WW / TILE)    // 16
#define TYN   (HH / TILE)    // 16
#define LPP   4
#define NPIX  (TILE * TILE)  // 64
#define THREADS (NPIX * LPP) // 256
#define PPT   (NP / THREADS) // 16 points per thread
#define CAPS  1024           // smem candidate capacity (~3x max observed)

#define ZINF 3.0e38f

__global__ void __launch_bounds__(THREADS) raster_fused(
        const float* __restrict__ pts,
        const float* __restrict__ Rm,
        const float* __restrict__ Tv,
        const float* __restrict__ Fc,
        float* __restrict__ out) {
    __shared__ float4 sc[CAPS];    // 16 KB candidate list
    __shared__ int s_cnt;

    const int bx = blockIdx.x, by = blockIdx.y, b = blockIdx.z;
    const int tid = threadIdx.x;

    if (tid == 0) s_cnt = 0;
    __syncthreads();

    // Uniform per-batch camera params (broadcast loads)
    const float* Rb = Rm + b * 9;
    const float* Tb = Tv + b * 3;
    const float r00 = Rb[0], r01 = Rb[1], r02 = Rb[2];
    const float r10 = Rb[3], r11 = Rb[4], r12 = Rb[5];
    const float r20 = Rb[6], r21 = Rb[7], r22 = Rb[8];
    const float t0 = Tb[0], t1 = Tb[1], t2 = Tb[2];
    const float f  = Fc[b];

    // Tile NDC bounds (gx decreases with pixel x); conservative expand by RAD
    const float gx_hi = 1.0f - ((float)(TILE * bx) + 0.5f) * (1.0f / 64.0f);
    const float gx_lo = 1.0f - ((float)(TILE * bx + TILE - 1) + 0.5f) * (1.0f / 64.0f);
    const float gy_hi = 1.0f - ((float)(TILE * by) + 0.5f) * (1.0f / 64.0f);
    const float gy_lo = 1.0f - ((float)(TILE * by + TILE - 1) + 0.5f) * (1.0f / 64.0f);
    const float bx_lo = gx_lo - RAD, bx_hi = gx_hi + RAD;
    const float by_lo = gy_lo - RAD, by_hi = gy_hi + RAD;

    // ====== Phase 1: redundant transform; thread owns 16 CONSECUTIVE points ==
    // Contiguous per-thread loads: 3 float4 = 4 points per iteration.
    {
        const float4* pb4 = (const float4*)(pts + (size_t)b * NP * 3);
        int p0i = tid * PPT;                  // first point index for this thread
#pragma unroll
        for (int it = 0; it < PPT / 4; it++) {
            int pbase = p0i + it * 4;
            int f4 = (pbase * 3) >> 2;        // float4 index (pbase*3 divisible by 4)
            float4 A = pb4[f4 + 0];
            float4 Bv = pb4[f4 + 1];
            float4 C = pb4[f4 + 2];
            float px3[4], py3[4], pz3[4];
            px3[0] = A.x;  py3[0] = A.y;  pz3[0] = A.z;
            px3[1] = A.w;  py3[1] = Bv.x; pz3[1] = Bv.y;
            px3[2] = Bv.z; py3[2] = Bv.w; pz3[2] = C.x;
            px3[3] = C.y;  py3[3] = C.z;  pz3[3] = C.w;
#pragma unroll
            for (int i = 0; i < 4; i++) {
                float p0 = px3[i], p1 = py3[i], p2 = pz3[i];
                // row-vector: v[j] = sum_i p[i]*R[i][j] + T[j]  (same expr as ref)
                float xv = p0 * r00 + p1 * r10 + p2 * r20 + t0;
                float yv = p0 * r01 + p1 * r11 + p2 * r21 + t1;
                float zv = p0 * r02 + p1 * r12 + p2 * r22 + t2;
                float x = f * xv / zv;        // IEEE div, matches reference
                float y = f * yv / zv;
                if (zv > 0.0f && x > bx_lo && x < bx_hi && y > by_lo && y < by_hi) {
                    int pos = atomicAdd(&s_cnt, 1);
                    if (pos < CAPS)
                        sc[pos] = make_float4(x, y, zv, (float)(pbase + i));
                }
            }
        }
    }
    __syncthreads();
    const int n = min(s_cnt, CAPS);

    // ====== Phase 2: raster — 4 lanes per pixel, branch-free ladder ==========
    const int grp = tid >> 2;      // pixel 0..63
    const int sub = tid & 3;       // lane within pixel
    const int lx = grp & (TILE - 1), ly = grp / TILE;
    const int px = bx * TILE + lx;
    const int py = by * TILE + ly;
    const float gx = 1.0f - (px + 0.5f) * (1.0f / 64.0f);
    const float gy = 1.0f - (py + 0.5f) * (1.0f / 64.0f);

    float zb[KK];
#pragma unroll
    for (int k = 0; k < KK; k++) zb[k] = ZINF;

    // ---- Pass 1: FMNMX ladder over smem list, lane scans j%4==sub ----------
    for (int j = sub; j < n; j += LPP) {
        float4 c = sc[j];
        float dx = gx - c.x;
        float dy = gy - c.y;
        float d2 = fmaf(dx, dx, dy * dy);
        float key = (d2 < RAD2) ? c.z : ZINF;
#pragma unroll
        for (int k = 0; k < KK; k++) {
            float lo = fminf(zb[k], key);
            key = fmaxf(zb[k], key);
            zb[k] = lo;
        }
    }

    // ---- merge 4 sorted lists: two bitonic-merge rounds (xor 1, xor 2) ------
#pragma unroll
    for (int d = 1; d <= 2; d <<= 1) {
        float L[KK];
#pragma unroll
        for (int k = 0; k < KK; k++) {
            float bk = __shfl_xor_sync(0xffffffffu, zb[KK - 1 - k], d);
            L[k] = fminf(zb[k], bk);          // lower half of bitonic merge
        }
#define CE(a, b2) { float lo = fminf(L[a], L[b2]); float hi = fmaxf(L[a], L[b2]); L[a] = lo; L[b2] = hi; }
        CE(0, 4) CE(1, 5) CE(2, 6) CE(3, 7)
        CE(0, 2) CE(1, 3) CE(4, 6) CE(5, 7)
        CE(0, 1) CE(2, 3) CE(4, 5) CE(6, 7)
#undef CE
#pragma unroll
        for (int k = 0; k < KK; k++) zb[k] = L[k];
    }
    const float z7 = zb[KK - 1];

    float db[KK], ib[KK];
#pragma unroll
    for (int k = 0; k < KK; k++) { db[k] = -1.0f; ib[k] = -1.0f; }

    // ---- Pass 2: sparse equality fill of d2/idx (z values distinct) ---------
    for (int j = sub; j < n; j += LPP) {
        float4 c = sc[j];
        float dx = gx - c.x;
        float dy = gy - c.y;
        float d2 = fmaf(dx, dx, dy * dy);
        if (d2 < RAD2 && c.z <= z7) {
#pragma unroll
            for (int k = 0; k < KK; k++) {
                if (c.z == zb[k]) { db[k] = d2; ib[k] = c.w; }
            }
        }
    }

    // ---- combine lane fills (unfilled = -1, filled >= 0 => max) -------------
#pragma unroll
    for (int d = 1; d <= 2; d <<= 1) {
#pragma unroll
        for (int k = 0; k < KK; k++) {
            db[k] = fmaxf(db[k], __shfl_xor_sync(0xffffffffu, db[k], d));
            ib[k] = fmaxf(ib[k], __shfl_xor_sync(0xffffffffu, ib[k], d));
        }
    }

    // ---- Output: [idx | zbuf | dists], each [B,H,W,K]; lanes split k --------
    const int N = BATCH * HH * WW * KK;
    const int obase = ((b * HH + py) * WW + px) * KK;
#pragma unroll
    for (int k2 = 0; k2 < KK / LPP; k2++) {
        int k = sub * (KK / LPP) + k2;
        bool v = zb[k] < ZINF;
        out[obase + k]         = v ? ib[k] : -1.0f;
        out[N + obase + k]     = v ? zb[k] : -1.0f;
        out[2 * N + obase + k] = v ? db[k] : -1.0f;
    }
}

// ---------------------------------------------------------------------------
extern "C" void kernel_launch(void* const* d_in, const int* in_sizes, int n_in,
                              void* d_out, int out_size) {
    const float* pts = (const float*)d_in[0];
    const float* Rm  = (const float*)d_in[1];
    const float* Tv  = (const float*)d_in[2];
    const float* Fc  = (const float*)d_in[3];
    float* out = (float*)d_out;

    raster_fused<<<dim3(TX, TYN, BATCH), THREADS>>>(pts, Rm, Tv, Fc, out);
}